// round 5
// baseline (speedup 1.0000x reference)
#include <cuda_runtime.h>

#define E_ROWS 100000
#define TS 132   // row stride (floats) for activation buffers: padded, keeps float4 alignment

typedef unsigned long long ull;

__device__ __forceinline__ ull pk2(float x, float y){
    ull r; asm("mov.b64 %0,{%1,%2};" : "=l"(r) : "f"(x), "f"(y)); return r;
}
__device__ __forceinline__ void fma2(ull& d, ull a, ull b){
    asm("fma.rn.f32x2 %0,%1,%2,%0;" : "+l"(d) : "l"(a), "l"(b));
}
__device__ __forceinline__ float2 up2(ull v){
    float2 r; asm("mov.b64 {%0,%1},%2;" : "=f"(r.x), "=f"(r.y) : "l"(v)); return r;
}
__device__ __forceinline__ float silu_f(float x){ return x / (1.0f + __expf(-x)); }

// GEMM: out[r][c] = silu(scale * sum_k in[r][k] * W[k][c])
// in: [128][TS] row-major smem, W: [K][128] row-major smem, out: [128][TS]
// 256 threads, per-thread tile 8 rows x 8 cols, f32x2 column-paired accumulators.
template<int K>
__device__ void gemm_act(const float* __restrict__ sIn, const float* __restrict__ sW,
                         float* __restrict__ sOut, int tid, float scale)
{
    const int cg = tid & 15, rg = tid >> 4;
    const int r0 = rg * 8, c0 = cg * 8;
    ull acc[8][4];
    #pragma unroll
    for (int i = 0; i < 8; i++)
        #pragma unroll
        for (int j = 0; j < 4; j++) acc[i][j] = 0ull;

    #pragma unroll 2
    for (int k = 0; k < K; k += 4) {
        float4 a4[8];
        #pragma unroll
        for (int i = 0; i < 8; i++)
            a4[i] = *(const float4*)(sIn + (r0 + i) * TS + k);
        #pragma unroll
        for (int kk = 0; kk < 4; kk++) {
            const float* wk = sW + (k + kk) * 128 + c0;
            ulonglong2 b01 = *(const ulonglong2*)(wk);
            ulonglong2 b23 = *(const ulonglong2*)(wk + 4);
            #pragma unroll
            for (int i = 0; i < 8; i++) {
                float av = (kk == 0) ? a4[i].x : (kk == 1) ? a4[i].y : (kk == 2) ? a4[i].z : a4[i].w;
                ull a2 = pk2(av, av);
                fma2(acc[i][0], a2, b01.x);
                fma2(acc[i][1], a2, b01.y);
                fma2(acc[i][2], a2, b23.x);
                fma2(acc[i][3], a2, b23.y);
            }
        }
    }
    #pragma unroll
    for (int i = 0; i < 8; i++) {
        float o[8];
        #pragma unroll
        for (int j = 0; j < 4; j++) {
            float2 p = up2(acc[i][j]);
            o[2*j]   = silu_f(p.x * scale);
            o[2*j+1] = silu_f(p.y * scale);
        }
        float4* dst = (float4*)(sOut + (r0 + i) * TS + c0);
        dst[0] = make_float4(o[0], o[1], o[2], o[3]);
        dst[1] = make_float4(o[4], o[5], o[6], o[7]);
    }
}

__global__ __launch_bounds__(256, 1)
void tpmlp_kernel(const float* __restrict__ emb, const float* __restrict__ x1,
                  const float* __restrict__ x2,  const float* __restrict__ W0,
                  const float* __restrict__ W1,  const float* __restrict__ P1,
                  const float* __restrict__ P2,  const float* __restrict__ P3,
                  const float* __restrict__ P4,  const float* __restrict__ P5,
                  float* __restrict__ out)
{
    extern __shared__ float smem[];
    float* sA  = smem;                 // 128*TS  : emb tile, later h2
    float* sB  = sA + 128 * TS;        // 128*TS  : h1
    float* sW  = sB + 128 * TS;        // 128*160 : W0 / W1 / P-chunk
    float* sX2 = sW + 128 * 160;       // 128*4

    const int tid  = threadIdx.x;
    const int row0 = blockIdx.x * 128;

    // --- stage emb tile [128][64] (float4, zero-padded past E) ---
    for (int idx = tid; idx < 128 * 16; idx += 256) {
        int r = idx >> 4, c4 = idx & 15;
        int gr = row0 + r;
        float4 v = make_float4(0.f, 0.f, 0.f, 0.f);
        if (gr < E_ROWS) v = ((const float4*)emb)[(size_t)gr * 16 + c4];
        *(float4*)(sA + r * TS + c4 * 4) = v;
    }
    // --- stage W0 [64][128] ---
    for (int idx = tid; idx < 64 * 32; idx += 256)
        ((float4*)sW)[idx] = ((const float4*)W0)[idx];
    // --- stage x2 tile [128][4] ---
    for (int idx = tid; idx < 512; idx += 256) {
        int r = idx >> 2, gr = row0 + r;
        sX2[idx] = (gr < E_ROWS) ? x2[(size_t)gr * 4 + (idx & 3)] : 0.f;
    }
    __syncthreads();

    // h1 = silu(emb @ W0 / sqrt(64))
    gemm_act<64>(sA, sW, sB, tid, 0.125f);
    __syncthreads();

    // --- stage W1 [128][128] ---
    for (int idx = tid; idx < 128 * 32; idx += 256)
        ((float4*)sW)[idx] = ((const float4*)W1)[idx];
    __syncthreads();

    // h2 = silu(h1 @ W1 / sqrt(128))
    gemm_act<128>(sB, sW, sA, tid, 0.08838834764831845f);
    __syncthreads();

    const float* Pm[5] = {P1, P2, P3, P4, P5};

    // GEMM3 + combine: per-thread tile = 8 rows x 2 u x 5 w (u-paired f32x2)
    const int ug = tid & 15, rg = tid >> 4;
    const int r0 = rg * 8;

    const float SC = 0.08838834764831845f; // 1/sqrt(128)
    const float C0 = 0.7071067811865476f;  // 1/sqrt(2)
    const float C3 = 0.5773502691896258f;  // 1/sqrt(3)
    const float C6 = 0.4082482904638630f;  // 1/sqrt(6)

    for (int ch = 0; ch < 2; ch++) {
        const int u0 = ch * 32;
        // stage P chunk as [k][m][32u] so b-operands are packed LDS.64 pairs
        #pragma unroll
        for (int m = 0; m < 5; m++) {
            const float* Pp = Pm[m];
            for (int idx = tid; idx < 128 * 32; idx += 256) {
                int k = idx >> 5, ul = idx & 31;
                sW[k * 160 + m * 32 + ul] = Pp[k * 64 + u0 + ul];
            }
        }
        __syncthreads();

        ull acc[8][5];
        #pragma unroll
        for (int i = 0; i < 8; i++)
            #pragma unroll
            for (int m = 0; m < 5; m++) acc[i][m] = 0ull;

        #pragma unroll 2
        for (int k = 0; k < 128; k += 4) {
            float4 a4[8];
            #pragma unroll
            for (int i = 0; i < 8; i++)
                a4[i] = *(const float4*)(sA + (r0 + i) * TS + k);
            #pragma unroll
            for (int kk = 0; kk < 4; kk++) {
                const float* wk = sW + (k + kk) * 160 + 2 * ug;
                ull b[5];
                #pragma unroll
                for (int m = 0; m < 5; m++) b[m] = *(const ull*)(wk + m * 32);
                #pragma unroll
                for (int i = 0; i < 8; i++) {
                    float av = (kk == 0) ? a4[i].x : (kk == 1) ? a4[i].y : (kk == 2) ? a4[i].z : a4[i].w;
                    ull a2 = pk2(av, av);
                    #pragma unroll
                    for (int m = 0; m < 5; m++) fma2(acc[i][m], a2, b[m]);
                }
            }
        }

        // combine + writeout for u in {u0+2*ug, u0+2*ug+1}, rows r0..r0+7
        #pragma unroll
        for (int i = 0; i < 8; i++) {
            int lr = r0 + i;
            int gr = row0 + lr;
            if (gr >= E_ROWS) continue;
            float x20 = sX2[lr * 4 + 0];
            float y0  = sX2[lr * 4 + 1];
            float y1  = sX2[lr * 4 + 2];
            float y2  = sX2[lr * 4 + 3];
            const float* x1r  = x1  + (size_t)gr * 256;
            float*       outr = out + (size_t)gr * 448;
            float2 q[5];
            #pragma unroll
            for (int m = 0; m < 5; m++) q[m] = up2(acc[i][m]);
            #pragma unroll
            for (int t = 0; t < 2; t++) {
                int u = u0 + 2 * ug + t;
                float w1 = (t ? q[0].y : q[0].x) * SC;
                float w2 = (t ? q[1].y : q[1].x) * SC;
                float w3 = (t ? q[2].y : q[2].x) * SC;
                float w4 = (t ? q[3].y : q[3].x) * SC;
                float w5 = (t ? q[4].y : q[4].x) * SC;
                float x10 = x1r[u];
                float a0  = x1r[64 + 3 * u + 0];
                float a1  = x1r[64 + 3 * u + 1];
                float a2v = x1r[64 + 3 * u + 2];
                float dt  = a0 * y0 + a1 * y1 + a2v * y2;
                outr[u] = C0 * (w1 * x10 * x20 + w4 * dt * C3);
                outr[64 + 3 * u + 0] = C0 * (w2 * a0  * x20 + w3 * x10 * y0);
                outr[64 + 3 * u + 1] = C0 * (w2 * a1  * x20 + w3 * x10 * y1);
                outr[64 + 3 * u + 2] = C0 * (w2 * a2v * x20 + w3 * x10 * y2);
                float c0v = a1  * y2 - a2v * y1;
                float c1v = a2v * y0 - a0  * y2;
                float c2v = a0  * y1 - a1  * y0;
                outr[256 + 3 * u + 0] = C6 * w5 * c0v;
                outr[256 + 3 * u + 1] = C6 * w5 * c1v;
                outr[256 + 3 * u + 2] = C6 * w5 * c2v;
            }
        }
        __syncthreads();
    }
}

extern "C" void kernel_launch(void* const* d_in, const int* in_sizes, int n_in,
                              void* d_out, int out_size)
{
    const float* emb = (const float*)d_in[0];
    const float* x1  = (const float*)d_in[1];
    const float* x2  = (const float*)d_in[2];
    const float* W0  = (const float*)d_in[3];
    const float* W1  = (const float*)d_in[4];
    const float* P1  = (const float*)d_in[5];
    const float* P2  = (const float*)d_in[6];
    const float* P3  = (const float*)d_in[7];
    const float* P4  = (const float*)d_in[8];
    const float* P5  = (const float*)d_in[9];
    float* out = (float*)d_out;

    const size_t smem_bytes = (size_t)(2 * 128 * TS + 128 * 160 + 512) * sizeof(float); // 219136 B
    cudaFuncSetAttribute(tpmlp_kernel, cudaFuncAttributeMaxDynamicSharedMemorySize, (int)smem_bytes);

    dim3 grid((E_ROWS + 127) / 128);  // 782 CTAs, 128 rows each
    tpmlp_kernel<<<grid, 256, smem_bytes>>>(emb, x1, x2, W0, W1, P1, P2, P3, P4, P5, out);
}

// round 9
// speedup vs baseline: 1.0516x; 1.0516x over previous
#include <cuda_runtime.h>

#define E_ROWS 100000
#define TS 132   // padded row stride (floats) for activation buffers

typedef unsigned long long ull;

__device__ __forceinline__ void fma2(ull& d, ull a, ull b){
    asm("fma.rn.f32x2 %0,%1,%2,%0;" : "+l"(d) : "l"(a), "l"(b));
}
__device__ __forceinline__ float2 up2(ull v){
    float2 r; asm("mov.b64 {%0,%1},%2;" : "=f"(r.x), "=f"(r.y) : "l"(v)); return r;
}
__device__ __forceinline__ ull pk2(float x, float y){
    ull r; asm("mov.b64 %0,{%1,%2};" : "=l"(r) : "f"(x), "f"(y)); return r;
}
__device__ __forceinline__ float silu_f(float x){ return x / (1.0f + __expf(-x)); }

// out[r][c] = silu(scale * sum_k in[r][k] * W[k][c])
// sIn: [128][TS] f32.  sWp: ull[KP*128], sWp[kp*128+c] = {W[2kp][c], W[2kp+1][c]}.
// 512 threads; per-thread 4 rows x 8 cols (cols strided by 16).
// f32x2 accumulators hold (even-k, odd-k) partial sums; merged in epilogue.
template<int KP>
__device__ __forceinline__ void gemm_act(const float* __restrict__ sIn,
                                         const ull* __restrict__ sWp,
                                         float* __restrict__ sOut,
                                         int tid, float scale)
{
    const int cg = tid & 15;
    const int r0 = (tid >> 4) * 4;
    ull acc[4][8];
    #pragma unroll
    for (int i = 0; i < 4; i++)
        #pragma unroll
        for (int j = 0; j < 8; j++) acc[i][j] = 0ull;

    #pragma unroll 4
    for (int kq = 0; kq < KP; kq += 2) {      // two k-pairs (4 k) per iteration
        ulonglong2 a2[4];                      // a2[i].x = {a[k0],a[k1]}, .y = {a[k2],a[k3]}
        #pragma unroll
        for (int i = 0; i < 4; i++)
            a2[i] = *(const ulonglong2*)(sIn + (r0 + i) * TS + 2 * kq);
        #pragma unroll
        for (int kk = 0; kk < 2; kk++) {
            const ull* wk = sWp + (kq + kk) * 128 + cg;
            ull b[8];
            #pragma unroll
            for (int j = 0; j < 8; j++) b[j] = wk[16 * j];
            #pragma unroll
            for (int i = 0; i < 4; i++) {
                ull a = kk ? a2[i].y : a2[i].x;
                #pragma unroll
                for (int j = 0; j < 8; j++) fma2(acc[i][j], a, b[j]);
            }
        }
    }
    #pragma unroll
    for (int i = 0; i < 4; i++)
        #pragma unroll
        for (int j = 0; j < 8; j++) {
            float2 p = up2(acc[i][j]);
            sOut[(r0 + i) * TS + cg + 16 * j] = silu_f((p.x + p.y) * scale);
        }
}

__global__ __launch_bounds__(512, 1)
void tpmlp_kernel(const float* __restrict__ emb, const float* __restrict__ x1,
                  const float* __restrict__ x2,  const float* __restrict__ W0,
                  const float* __restrict__ W1,  const float* __restrict__ P1,
                  const float* __restrict__ P2,  const float* __restrict__ P3,
                  const float* __restrict__ P4,  const float* __restrict__ P5,
                  float* __restrict__ out)
{
    extern __shared__ float smem[];
    float* sA  = smem;                     // 128*TS : emb tile, later h2
    float* sB  = sA + 128 * TS;            // 128*TS : h1
    ull*   sWp = (ull*)(sB + 128 * TS);    // 8192 ull (64KB): packed W0/W1/P-chunk
    float* sX2 = (float*)(sWp + 8192);     // 128*4

    const int tid  = threadIdx.x;
    const int row0 = blockIdx.x * 128;

    // --- stage emb tile [128][64] ---
    for (int idx = tid; idx < 128 * 16; idx += 512) {
        int r = idx >> 4, c4 = idx & 15;
        int gr = row0 + r;
        float4 v = make_float4(0.f, 0.f, 0.f, 0.f);
        if (gr < E_ROWS) v = ((const float4*)emb)[(size_t)gr * 16 + c4];
        *(float4*)(sA + r * TS + c4 * 4) = v;
    }
    // --- stage W0 as k-pair-packed ulls: 32 kp x 128 c ---
    for (int idx = tid; idx < 32 * 128; idx += 512) {
        int c = idx & 127, kp = idx >> 7;
        sWp[idx] = pk2(W0[2 * kp * 128 + c], W0[(2 * kp + 1) * 128 + c]);
    }
    // --- stage x2 tile [128][4] ---
    {
        int r = tid >> 2, gr = row0 + r;
        sX2[tid] = (gr < E_ROWS) ? x2[(size_t)gr * 4 + (tid & 3)] : 0.f;
    }
    __syncthreads();

    // h1 = silu(emb @ W0 / sqrt(64))
    gemm_act<32>(sA, sWp, sB, tid, 0.125f);
    __syncthreads();

    // --- stage W1 packed: 64 kp x 128 c ---
    for (int idx = tid; idx < 64 * 128; idx += 512) {
        int c = idx & 127, kp = idx >> 7;
        sWp[idx] = pk2(W1[2 * kp * 128 + c], W1[(2 * kp + 1) * 128 + c]);
    }
    __syncthreads();

    // h2 = silu(h1 @ W1 / sqrt(128))
    gemm_act<64>(sB, sWp, sA, tid, 0.08838834764831845f);
    __syncthreads();

    const float* Pm[5] = {P1, P2, P3, P4, P5};

    const float SC = 0.08838834764831845f; // 1/sqrt(128)
    const float C0 = 0.7071067811865476f;  // 1/sqrt(2)
    const float C3 = 0.5773502691896258f;  // 1/sqrt(3)
    const float C6 = 0.4082482904638630f;  // 1/sqrt(6)

    // GEMM3 + combine: 4 chunks of 16 u. Per-thread: 4 rows x 1 u x 5 m.
    const int ug = tid & 15;
    const int r0 = (tid >> 4) * 4;
    ull* sPp = sWp;  // reuse weight buffer: 64kp*5m*16u = 5120 ull (40KB)

    for (int ch = 0; ch < 4; ch++) {
        const int u0 = ch * 16;
        // stage P chunk: sPp[kp*80 + m*16 + uu] = {P_m[2kp][u0+uu], P_m[2kp+1][u0+uu]}
        for (int idx = tid; idx < 5120; idx += 512) {
            int uu = idx & 15;
            int m  = (idx >> 4) % 5;
            int kp = idx / 80;
            const float* Pp = Pm[m];
            sPp[idx] = pk2(Pp[2 * kp * 64 + u0 + uu], Pp[(2 * kp + 1) * 64 + u0 + uu]);
        }
        __syncthreads();

        ull acc[4][5];
        #pragma unroll
        for (int i = 0; i < 4; i++)
            #pragma unroll
            for (int m = 0; m < 5; m++) acc[i][m] = 0ull;

        #pragma unroll 4
        for (int kq = 0; kq < 64; kq += 2) {
            ulonglong2 a2[4];
            #pragma unroll
            for (int i = 0; i < 4; i++)
                a2[i] = *(const ulonglong2*)(sA + (r0 + i) * TS + 2 * kq);
            #pragma unroll
            for (int kk = 0; kk < 2; kk++) {
                const ull* bp = sPp + (kq + kk) * 80 + ug;
                ull b[5];
                #pragma unroll
                for (int m = 0; m < 5; m++) b[m] = bp[16 * m];
                #pragma unroll
                for (int i = 0; i < 4; i++) {
                    ull a = kk ? a2[i].y : a2[i].x;
                    #pragma unroll
                    for (int m = 0; m < 5; m++) fma2(acc[i][m], a, b[m]);
                }
            }
        }

        // combine + writeout: u = u0 + ug, rows r0..r0+3
        const int u = u0 + ug;
        #pragma unroll
        for (int i = 0; i < 4; i++) {
            int lr = r0 + i;
            int gr = row0 + lr;
            if (gr >= E_ROWS) continue;
            float x20 = sX2[lr * 4 + 0];
            float y0  = sX2[lr * 4 + 1];
            float y1  = sX2[lr * 4 + 2];
            float y2  = sX2[lr * 4 + 3];
            float w[5];
            #pragma unroll
            for (int m = 0; m < 5; m++) {
                float2 p = up2(acc[i][m]);
                w[m] = (p.x + p.y) * SC;
            }
            const float* x1r  = x1  + (size_t)gr * 256;
            float*       outr = out + (size_t)gr * 448;
            float x10 = x1r[u];
            float a0  = x1r[64 + 3 * u + 0];
            float a1  = x1r[64 + 3 * u + 1];
            float a2v = x1r[64 + 3 * u + 2];
            float dt  = a0 * y0 + a1 * y1 + a2v * y2;
            outr[u] = C0 * (w[0] * x10 * x20 + w[3] * dt * C3);
            outr[64 + 3 * u + 0] = C0 * (w[1] * a0  * x20 + w[2] * x10 * y0);
            outr[64 + 3 * u + 1] = C0 * (w[1] * a1  * x20 + w[2] * x10 * y1);
            outr[64 + 3 * u + 2] = C0 * (w[1] * a2v * x20 + w[2] * x10 * y2);
            outr[256 + 3 * u + 0] = C6 * w[4] * (a1  * y2 - a2v * y1);
            outr[256 + 3 * u + 1] = C6 * w[4] * (a2v * y0 - a0  * y2);
            outr[256 + 3 * u + 2] = C6 * w[4] * (a0  * y1 - a1  * y0);
        }
        __syncthreads();
    }
}

extern "C" void kernel_launch(void* const* d_in, const int* in_sizes, int n_in,
                              void* d_out, int out_size)
{
    const float* emb = (const float*)d_in[0];
    const float* x1  = (const float*)d_in[1];
    const float* x2  = (const float*)d_in[2];
    const float* W0  = (const float*)d_in[3];
    const float* W1  = (const float*)d_in[4];
    const float* P1  = (const float*)d_in[5];
    const float* P2  = (const float*)d_in[6];
    const float* P3  = (const float*)d_in[7];
    const float* P4  = (const float*)d_in[8];
    const float* P5  = (const float*)d_in[9];
    float* out = (float*)d_out;

    // 2*128*132 floats + 8192 ull + 512 floats = 202,752 B
    const size_t smem_bytes = (size_t)(2 * 128 * TS) * sizeof(float)
                            + 8192 * sizeof(ull) + 512 * sizeof(float);
    cudaFuncSetAttribute(tpmlp_kernel, cudaFuncAttributeMaxDynamicSharedMemorySize, (int)smem_bytes);

    dim3 grid((E_ROWS + 127) / 128);  // 782 CTAs
    tpmlp_kernel<<<grid, 512, smem_bytes>>>(emb, x1, x2, W0, W1, P1, P2, P3, P4, P5, out);
}

// round 10
// speedup vs baseline: 1.0718x; 1.0192x over previous
#include <cuda_runtime.h>

#define E_ROWS 100000
#define TS 132   // padded row stride (floats) for activation buffers

typedef unsigned long long ull;

__device__ __forceinline__ void fma2(ull& d, ull a, ull b){
    asm("fma.rn.f32x2 %0,%1,%2,%0;" : "+l"(d) : "l"(a), "l"(b));
}
__device__ __forceinline__ float2 up2(ull v){
    float2 r; asm("mov.b64 {%0,%1},%2;" : "=f"(r.x), "=f"(r.y) : "l"(v)); return r;
}
__device__ __forceinline__ ull pk2(float x, float y){
    ull r; asm("mov.b64 %0,{%1,%2};" : "=l"(r) : "f"(x), "f"(y)); return r;
}
__device__ __forceinline__ float silu_f(float x){ return x / (1.0f + __expf(-x)); }

// out[r][c] = silu(scale * sum_k in[r][k] * W[k][c])
// sIn: [128][TS] f32.  sWp: ull[KP*128], sWp[kp*128+c] = {W[2kp][c], W[2kp+1][c]}.
// 512 threads. Per-thread 8 rows x 4 cols (c = lane + 32j).
// A loads are FULL-WARP broadcast LDS.128; B reuse = 8 rows -> 64B/cyc crossbar at peak.
// f32x2 accumulators hold (even-k, odd-k) partial sums; merged in epilogue.
template<int KP>
__device__ __forceinline__ void gemm_act(const float* __restrict__ sIn,
                                         const ull* __restrict__ sWp,
                                         float* __restrict__ sOut,
                                         int tid, float scale)
{
    const int cg = tid & 31;           // lane = column group
    const int r0 = (tid >> 5) * 8;     // warp id = 8-row group
    ull acc[8][4];
    #pragma unroll
    for (int i = 0; i < 8; i++)
        #pragma unroll
        for (int j = 0; j < 4; j++) acc[i][j] = 0ull;

    #pragma unroll 2
    for (int kq = 0; kq < KP; kq += 2) {      // two k-pairs (4 k) per iteration
        ull b0[4], b1[4];
        const ull* w0 = sWp + kq * 128 + cg;
        #pragma unroll
        for (int j = 0; j < 4; j++) { b0[j] = w0[32 * j]; b1[j] = w0[128 + 32 * j]; }
        #pragma unroll
        for (int h = 0; h < 2; h++) {          // 2 half-tiles of 4 rows: caps live regs
            ulonglong2 a2[4];                  // .x = {a[k0],a[k1]}, .y = {a[k2],a[k3]}
            #pragma unroll
            for (int i = 0; i < 4; i++)
                a2[i] = *(const ulonglong2*)(sIn + (r0 + 4 * h + i) * TS + 2 * kq);
            #pragma unroll
            for (int i = 0; i < 4; i++) {
                #pragma unroll
                for (int j = 0; j < 4; j++) fma2(acc[4 * h + i][j], a2[i].x, b0[j]);
                #pragma unroll
                for (int j = 0; j < 4; j++) fma2(acc[4 * h + i][j], a2[i].y, b1[j]);
            }
        }
    }
    #pragma unroll
    for (int i = 0; i < 8; i++)
        #pragma unroll
        for (int j = 0; j < 4; j++) {
            float2 p = up2(acc[i][j]);
            sOut[(r0 + i) * TS + cg + 32 * j] = silu_f((p.x + p.y) * scale);
        }
}

__global__ __launch_bounds__(512, 1)
void tpmlp_kernel(const float* __restrict__ emb, const float* __restrict__ x1,
                  const float* __restrict__ x2,  const float* __restrict__ W0,
                  const float* __restrict__ W1,  const float* __restrict__ P1,
                  const float* __restrict__ P2,  const float* __restrict__ P3,
                  const float* __restrict__ P4,  const float* __restrict__ P5,
                  float* __restrict__ out)
{
    extern __shared__ float smem[];
    float* sA  = smem;                     // 128*TS : emb tile, later h2
    float* sB  = sA + 128 * TS;            // 128*TS : h1 (dead after GEMM2)
    ull*   sWp = (ull*)(sB + 128 * TS);    // 8192 ull (64KB): packed W0/W1
    float* sX2 = (float*)(sWp + 8192);     // 128*4
    // GEMM3 P staging reuses sB..sWp contiguously: 10240 ull (80KB) fits in 131KB
    ull*   sPp = (ull*)sB;

    const int tid  = threadIdx.x;
    const int row0 = blockIdx.x * 128;

    // --- stage emb tile [128][64] ---
    for (int idx = tid; idx < 128 * 16; idx += 512) {
        int r = idx >> 4, c4 = idx & 15;
        int gr = row0 + r;
        float4 v = make_float4(0.f, 0.f, 0.f, 0.f);
        if (gr < E_ROWS) v = ((const float4*)emb)[(size_t)gr * 16 + c4];
        *(float4*)(sA + r * TS + c4 * 4) = v;
    }
    // --- stage W0 k-pair-packed: 32 kp x 128 c ---
    for (int idx = tid; idx < 32 * 128; idx += 512) {
        int c = idx & 127, kp = idx >> 7;
        sWp[idx] = pk2(W0[2 * kp * 128 + c], W0[(2 * kp + 1) * 128 + c]);
    }
    // --- stage x2 tile [128][4] ---
    {
        int r = tid >> 2, gr = row0 + r;
        sX2[tid] = (gr < E_ROWS) ? x2[(size_t)gr * 4 + (tid & 3)] : 0.f;
    }
    __syncthreads();

    // h1 = silu(emb @ W0 / sqrt(64))
    gemm_act<32>(sA, sWp, sB, tid, 0.125f);
    __syncthreads();

    // --- stage W1 packed: 64 kp x 128 c ---
    for (int idx = tid; idx < 64 * 128; idx += 512) {
        int c = idx & 127, kp = idx >> 7;
        sWp[idx] = pk2(W1[2 * kp * 128 + c], W1[(2 * kp + 1) * 128 + c]);
    }
    __syncthreads();

    // h2 = silu(h1 @ W1 / sqrt(128))
    gemm_act<64>(sB, sWp, sA, tid, 0.08838834764831845f);
    __syncthreads();

    const float* Pm[5] = {P1, P2, P3, P4, P5};

    const float SC = 0.08838834764831845f; // 1/sqrt(128)
    const float C0 = 0.7071067811865476f;  // 1/sqrt(2)
    const float C3 = 0.5773502691896258f;  // 1/sqrt(3)
    const float C6 = 0.4082482904638630f;  // 1/sqrt(6)

    // GEMM3 + combine: 2 chunks of 32 u. Per-thread: 4 rows x 1 u-PAIR x 5 m.
    // f32x2 accumulators pair adjacent u; b-loads are half-warp-broadcast packed pairs.
    const int ug = tid & 15;               // u-pair index within chunk
    const int r0 = (tid >> 4) * 4;         // 32 row groups x 4 rows

    for (int ch = 0; ch < 2; ch++) {
        const int u0 = ch * 32;
        // stage P chunk: sPp[k*80 + m*16 + p] = {P_m[k][u0+2p], P_m[k][u0+2p+1]}
        for (int idx = tid; idx < 10240; idx += 512) {
            int k   = idx / 80;
            int rem = idx - k * 80;
            int m   = rem >> 4, p = rem & 15;
            const float2 v = *(const float2*)(Pm[m] + k * 64 + u0 + 2 * p);
            sPp[idx] = pk2(v.x, v.y);
        }
        __syncthreads();

        ull acc[4][5];
        #pragma unroll
        for (int i = 0; i < 4; i++)
            #pragma unroll
            for (int m = 0; m < 5; m++) acc[i][m] = 0ull;

        #pragma unroll 2
        for (int k4 = 0; k4 < 128; k4 += 4) {
            float4 a4[4];
            #pragma unroll
            for (int i = 0; i < 4; i++)
                a4[i] = *(const float4*)(sA + (r0 + i) * TS + k4);
            #pragma unroll
            for (int kk = 0; kk < 4; kk++) {
                const ull* bp = sPp + (k4 + kk) * 80 + ug;
                ull b[5];
                #pragma unroll
                for (int m = 0; m < 5; m++) b[m] = bp[16 * m];
                #pragma unroll
                for (int i = 0; i < 4; i++) {
                    float av = (kk == 0) ? a4[i].x : (kk == 1) ? a4[i].y
                             : (kk == 2) ? a4[i].z : a4[i].w;
                    ull a = pk2(av, av);
                    #pragma unroll
                    for (int m = 0; m < 5; m++) fma2(acc[i][m], a, b[m]);
                }
            }
        }

        // combine + writeout: u = u0 + 2*ug + {0,1}, rows r0..r0+3
        #pragma unroll
        for (int i = 0; i < 4; i++) {
            int lr = r0 + i;
            int gr = row0 + lr;
            if (gr >= E_ROWS) continue;
            float x20 = sX2[lr * 4 + 0];
            float y0  = sX2[lr * 4 + 1];
            float y1  = sX2[lr * 4 + 2];
            float y2  = sX2[lr * 4 + 3];
            float2 q[5];
            #pragma unroll
            for (int m = 0; m < 5; m++) q[m] = up2(acc[i][m]);
            const float* x1r  = x1  + (size_t)gr * 256;
            float*       outr = out + (size_t)gr * 448;
            #pragma unroll
            for (int t = 0; t < 2; t++) {
                int u = u0 + 2 * ug + t;
                float w1 = (t ? q[0].y : q[0].x) * SC;
                float w2 = (t ? q[1].y : q[1].x) * SC;
                float w3 = (t ? q[2].y : q[2].x) * SC;
                float w4 = (t ? q[3].y : q[3].x) * SC;
                float w5 = (t ? q[4].y : q[4].x) * SC;
                float x10 = x1r[u];
                float a0  = x1r[64 + 3 * u + 0];
                float a1  = x1r[64 + 3 * u + 1];
                float a2v = x1r[64 + 3 * u + 2];
                float dt  = a0 * y0 + a1 * y1 + a2v * y2;
                outr[u] = C0 * (w1 * x10 * x20 + w4 * dt * C3);
                outr[64 + 3 * u + 0] = C0 * (w2 * a0  * x20 + w3 * x10 * y0);
                outr[64 + 3 * u + 1] = C0 * (w2 * a1  * x20 + w3 * x10 * y1);
                outr[64 + 3 * u + 2] = C0 * (w2 * a2v * x20 + w3 * x10 * y2);
                outr[256 + 3 * u + 0] = C6 * w5 * (a1  * y2 - a2v * y1);
                outr[256 + 3 * u + 1] = C6 * w5 * (a2v * y0 - a0  * y2);
                outr[256 + 3 * u + 2] = C6 * w5 * (a0  * y1 - a1  * y0);
            }
        }
        __syncthreads();
    }
}

extern "C" void kernel_launch(void* const* d_in, const int* in_sizes, int n_in,
                              void* d_out, int out_size)
{
    const float* emb = (const float*)d_in[0];
    const float* x1  = (const float*)d_in[1];
    const float* x2  = (const float*)d_in[2];
    const float* W0  = (const float*)d_in[3];
    const float* W1  = (const float*)d_in[4];
    const float* P1  = (const float*)d_in[5];
    const float* P2  = (const float*)d_in[6];
    const float* P3  = (const float*)d_in[7];
    const float* P4  = (const float*)d_in[8];
    const float* P5  = (const float*)d_in[9];
    float* out = (float*)d_out;

    // 2*128*132 floats + 8192 ull + 512 floats = 202,752 B
    const size_t smem_bytes = (size_t)(2 * 128 * TS) * sizeof(float)
                            + 8192 * sizeof(ull) + 512 * sizeof(float);
    cudaFuncSetAttribute(tpmlp_kernel, cudaFuncAttributeMaxDynamicSharedMemorySize, (int)smem_bytes);

    dim3 grid((E_ROWS + 127) / 128);  // 782 CTAs
    tpmlp_kernel<<<grid, 512, smem_bytes>>>(emb, x1, x2, W0, W1, P1, P2, P3, P4, P5, out);
}